// round 11
// baseline (speedup 1.0000x reference)
#include <cuda_runtime.h>
#include <cuda_fp16.h>
#include <math.h>
#include <stdint.h>

#define MR 2
#define NE 8
#define CD 1024
#define DD 256
#define BB 32
#define SS 512
#define STAGES 3
// stage (32KB): A0 8K | A1 8K | B0 8K | B1 8K  (CTA tile 128m x 128n x 64k)
// each sub-block keeps the round-10 verified layout/swizzle for 32 k
#define STAGE_BYTES 32768
#define OFF_B  16384
#define SMEM_TOTAL (STAGES * STAGE_BYTES)   // 98304; 2 CTAs/SM = 192KB

typedef __half fp16;

// ---------------- static device scratch (no allocs) ----------------
__device__ fp16 g_x[(size_t)BB * SS * CD];         // x fp16 (C contiguous)
__device__ fp16 g_z[(size_t)MR * BB * SS * DD];    // z fp16 (D contiguous)
__device__ fp16 g_dw16[(size_t)MR * NE * CD * DD]; // dw fp16, NATIVE [C][D]
__device__ fp16 g_uw16[(size_t)MR * NE * DD * CD]; // uw fp16, NATIVE [D][C]

// ---------------- ptx helpers ----------------
__device__ __forceinline__ uint32_t smem_u32(const void* p) {
    uint32_t a;
    asm("{ .reg .u64 t; cvta.to.shared.u64 t, %1; cvt.u32.u64 %0, t; }" : "=r"(a) : "l"(p));
    return a;
}
#define CP16(dst, src) \
    asm volatile("cp.async.cg.shared.global [%0], [%1], 16;" :: "r"(dst), "l"(src))
#define CP_COMMIT() asm volatile("cp.async.commit_group;")
#define CP_WAIT1()  asm volatile("cp.async.wait_group 1;")
#define CP_WAIT0()  asm volatile("cp.async.wait_group 0;")

#define LDSM4(r, a) \
    asm volatile("ldmatrix.sync.aligned.m8n8.x4.shared.b16 {%0,%1,%2,%3}, [%4];" \
        : "=r"((r)[0]), "=r"((r)[1]), "=r"((r)[2]), "=r"((r)[3]) : "r"(a))
#define LDSM4T(r, a) \
    asm volatile("ldmatrix.sync.aligned.m8n8.x4.trans.shared.b16 {%0,%1,%2,%3}, [%4];" \
        : "=r"((r)[0]), "=r"((r)[1]), "=r"((r)[2]), "=r"((r)[3]) : "r"(a))

#define MMA(d, a, b0, b1) \
    asm volatile("mma.sync.aligned.m16n8k16.row.col.f32.f16.f16.f32 " \
        "{%0,%1,%2,%3},{%4,%5,%6,%7},{%8,%9},{%0,%1,%2,%3};" \
        : "+f"((d)[0]), "+f"((d)[1]), "+f"((d)[2]), "+f"((d)[3]) \
        : "r"((a)[0]), "r"((a)[1]), "r"((a)[2]), "r"((a)[3]), "r"(b0), "r"(b1))

// A-side swizzle: 64B rows (4 x 16B chunks)
__device__ __forceinline__ uint32_t swz(uint32_t row, uint32_t chunk) {
    return row * 64u + ((chunk ^ ((row >> 1) & 3u)) << 4);
}
// B-side (K-major) swizzle: 256B rows (16 x 16B chunks), chunk ^= row&7
__device__ __forceinline__ uint32_t bswz(uint32_t row, uint32_t chunk) {
    return row * 256u + ((chunk ^ (row & 7u)) << 4);
}

// ---------------- stage loader: 8x cp.async(16B) per thread (K=64) -----------
// A: [128 m][64 k] as two 32k sub-blocks; B: [64 k][128 n] as two 32k sub-blocks
__device__ __forceinline__ void stage_load(uint32_t sbase,
                                           const fp16* __restrict__ A1, int lda,
                                           const fp16* __restrict__ Bg, int ldb,
                                           int ncol0, int kc, int tid) {
    #pragma unroll
    for (int kb = 0; kb < 2; kb++) {
        const uint32_t sa = sbase + kb * 8192;
        const uint32_t sb = sbase + OFF_B + kb * 8192;
        const int kk = kc + kb * 32;
        #pragma unroll
        for (int i = 0; i < 2; i++) {
            int q = tid + (i << 8);
            {   // A chunk: 512 = 128 rows x 4 chunks
                int r = q >> 2, c = q & 3;
                CP16(sa + swz(r, c), A1 + (size_t)r * lda + kk + c * 8);
            }
            {   // B chunk: 512 = 32 rows x 16 chunks
                int r = q >> 4, c = q & 15;
                CP16(sb + bswz(r, c), Bg + (size_t)(kk + r) * ldb + ncol0 + c * 8);
            }
        }
    }
}

// ---------------- GEMM mainloop: warp tile 64x32, K=64 per iter ---------------
__device__ __forceinline__ void gemm_main(uint32_t smem_b,
                                          const fp16* __restrict__ A1, int lda,
                                          const fp16* __restrict__ Bg, int ldb,
                                          int ncol0, int nk,
                                          float acc[4][4][4], int tid) {
    const int lane = tid & 31, warp = tid >> 5;
    const int wm = (warp & 1) * 64, wn = (warp >> 1) * 32;
    const int r15 = lane & 15, chi = lane >> 4;

    // frag offsets within an 8KB sub-block (round-10 verified)
    const uint32_t a0 = swz((uint32_t)(wm + r15), (uint32_t)chi);
    const uint32_t b0 = bswz((uint32_t)r15, (uint32_t)((wn >> 3) + chi));
    const uint32_t b1 = bswz((uint32_t)r15, (uint32_t)((wn >> 3) + 2 + chi));

    stage_load(smem_b,               A1, lda, Bg, ldb, ncol0, 0,  tid);  CP_COMMIT();
    stage_load(smem_b + STAGE_BYTES, A1, lda, Bg, ldb, ncol0, 64, tid);  CP_COMMIT();

    uint32_t ah[4][4], bb[2][4];
    int rs = 0, ps = 2;   // ring slots: current, prefetch

    for (int k = 0; k < nk; k++) {
        if (k + 2 < nk) { CP_WAIT1(); } else { CP_WAIT0(); }
        __syncthreads();   // stage k visible; reads of slot ps (= stage k-1) done
        if (k + 2 < nk) {
            stage_load(smem_b + ps * STAGE_BYTES, A1, lda, Bg, ldb, ncol0,
                       (k + 2) * 64, tid);
            CP_COMMIT();
            ps = (ps == 2) ? 0 : ps + 1;
        }
        const uint32_t stg = smem_b + rs * STAGE_BYTES;
        rs = (rs == 2) ? 0 : rs + 1;

        #pragma unroll
        for (int kb = 0; kb < 2; kb++) {
            const uint32_t asub = stg + kb * 8192;
            const uint32_t bsub = stg + OFF_B + kb * 8192;
            #pragma unroll
            for (int ks = 0; ks < 2; ks++) {
                const uint32_t ax = asub + (ks ? (a0 ^ 32u) : a0);
                const uint32_t bof = bsub + (ks ? 4096u : 0u);
                LDSM4T(bb[0], bof + b0);
                LDSM4T(bb[1], bof + b1);
                LDSM4(ah[0], ax);
                LDSM4(ah[1], ax + 1024);
                LDSM4(ah[2], ax + 2048);
                LDSM4(ah[3], ax + 3072);
                #pragma unroll
                for (int mt = 0; mt < 4; mt++)
                    #pragma unroll
                    for (int nt = 0; nt < 4; nt++)
                        MMA(acc[mt][nt], ah[mt],
                            bb[nt >> 1][2 * (nt & 1)], bb[nt >> 1][2 * (nt & 1) + 1]);
            }
        }
    }
}

// ---------------- down: z = silu(x @ dw + db), fp16 z -------------------------
__global__ void __launch_bounds__(256, 2)
down_mma(const int* __restrict__ eidx, const float* __restrict__ db) {
    extern __shared__ char smem[];
    uint32_t smem_b = smem_u32(smem);
    const int tid = threadIdx.x, lane = tid & 31, warp = tid >> 5;
    const int wm = (warp & 1) * 64, wn = (warp >> 1) * 32;
    const int stile = blockIdx.x >> 1, ntile = blockIdx.x & 1;
    const int b = blockIdx.y, m = blockIdx.z;
    const int e = eidx[m * BB + b];

    const fp16* A1 = g_x    + ((size_t)b * SS + stile * 128) * CD;
    const fp16* Bg = g_dw16 + (size_t)(m * NE + e) * CD * DD;   // [C][D] K-major

    float acc[4][4][4];
    #pragma unroll
    for (int i = 0; i < 4; i++)
        #pragma unroll
        for (int j = 0; j < 4; j++)
            #pragma unroll
            for (int q = 0; q < 4; q++) acc[i][j][q] = 0.f;

    gemm_main(smem_b, A1, CD, Bg, DD, ntile * 128, CD / 64, acc, tid);

    const float* bias = db + (size_t)(m * NE + e) * DD;
    const size_t zrow0 = ((size_t)(m * BB + b) * SS + stile * 128);
    const int r0 = lane >> 2, cp = 2 * (lane & 3);

    #pragma unroll
    for (int mt = 0; mt < 4; mt++) {
        #pragma unroll
        for (int nt = 0; nt < 4; nt++) {
            const int col = ntile * 128 + wn + nt * 8 + cp;
            const float2 bv = *reinterpret_cast<const float2*>(bias + col);
            #pragma unroll
            for (int h = 0; h < 2; h++) {
                float v0 = acc[mt][nt][2 * h + 0] + bv.x;
                float v1 = acc[mt][nt][2 * h + 1] + bv.y;
                v0 = v0 / (1.f + __expf(-v0));
                v1 = v1 / (1.f + __expf(-v1));
                __half2 hp; hp.x = __float2half(v0); hp.y = __float2half(v1);
                *reinterpret_cast<__half2*>(
                    g_z + (zrow0 + wm + mt * 16 + r0 + h * 8) * DD + col) = hp;
            }
        }
    }
}

// ---------------- up: out = z @ uw (fp32 out) --------------------------------
__global__ void __launch_bounds__(256, 2)
up_mma(const int* __restrict__ eidx, float* __restrict__ out) {
    extern __shared__ char smem[];
    uint32_t smem_b = smem_u32(smem);
    const int tid = threadIdx.x, lane = tid & 31, warp = tid >> 5;
    const int wm = (warp & 1) * 64, wn = (warp >> 1) * 32;
    const int stile = blockIdx.x & 3, ctile = blockIdx.x >> 2;
    const int b = blockIdx.y, m = blockIdx.z;
    const int e = eidx[m * BB + b];

    const fp16* A1 = g_z    + ((size_t)(m * BB + b) * SS + stile * 128) * DD;
    const fp16* Bg = g_uw16 + (size_t)(m * NE + e) * DD * CD;   // [D][C] K-major

    float acc[4][4][4];
    #pragma unroll
    for (int i = 0; i < 4; i++)
        #pragma unroll
        for (int j = 0; j < 4; j++)
            #pragma unroll
            for (int q = 0; q < 4; q++) acc[i][j][q] = 0.f;

    gemm_main(smem_b, A1, DD, Bg, CD, ctile * 128, DD / 64, acc, tid);

    const size_t orow0 = ((size_t)(m * BB + b) * SS + stile * 128);
    const int r0 = lane >> 2, cp = 2 * (lane & 3);

    #pragma unroll
    for (int mt = 0; mt < 4; mt++) {
        #pragma unroll
        for (int nt = 0; nt < 4; nt++) {
            const int col = ctile * 128 + wn + nt * 8 + cp;
            #pragma unroll
            for (int h = 0; h < 2; h++) {
                const size_t off = (orow0 + wm + mt * 16 + r0 + h * 8) * CD + col;
                *reinterpret_cast<float2*>(out + off) =
                    make_float2(acc[mt][nt][2 * h + 0], acc[mt][nt][2 * h + 1]);
            }
        }
    }
}

// ---------------- prep: fused fp32 -> fp16 conversion of x, dw, uw ------------
#define NX4 ((size_t)BB * SS * CD / 4)
#define NW4 ((size_t)MR * NE * CD * DD / 4)
__global__ void __launch_bounds__(256)
cvt_all(const float* __restrict__ x, const float* __restrict__ dw,
        const float* __restrict__ uw) {
    size_t g = (size_t)blockIdx.x * 256 + threadIdx.x;
    const float* src; fp16* dst; size_t i;
    if (g < NX4)            { src = x;  dst = g_x;    i = g; }
    else if (g < NX4 + NW4) { src = dw; dst = g_dw16; i = g - NX4; }
    else                    { src = uw; dst = g_uw16; i = g - NX4 - NW4; }
    float4 v = *reinterpret_cast<const float4*>(src + i * 4);
    __half2 p0, p1;
    p0.x = __float2half(v.x); p0.y = __float2half(v.y);
    p1.x = __float2half(v.z); p1.y = __float2half(v.w);
    *reinterpret_cast<uint2*>(dst + i * 4) =
        make_uint2(*reinterpret_cast<uint32_t*>(&p0), *reinterpret_cast<uint32_t*>(&p1));
}

// ---------------- launch ------------------------------------------------------
extern "C" void kernel_launch(void* const* d_in, const int* in_sizes, int n_in,
                              void* d_out, int out_size) {
    const float* x    = (const float*)d_in[0];   // [B,S,C]
    const int*   eidx = (const int*)d_in[1];     // [M,B]
    const float* dw   = (const float*)d_in[2];   // [M,N,C,D]
    const float* db   = (const float*)d_in[3];   // [M,N,D]
    const float* uw   = (const float*)d_in[4];   // [M,N,D,C]
    float*       out  = (float*)d_out;           // [M,B,S,C]

    cudaFuncSetAttribute(down_mma, cudaFuncAttributeMaxDynamicSharedMemorySize, SMEM_TOTAL);
    cudaFuncSetAttribute(up_mma,   cudaFuncAttributeMaxDynamicSharedMemorySize, SMEM_TOTAL);

    cvt_all<<<(unsigned)((NX4 + 2 * NW4) / 256), 256>>>(x, dw, uw);

    down_mma<<<dim3(8, BB, MR), 256, SMEM_TOTAL>>>(eidx, db);
    up_mma<<<dim3(32, BB, MR), 256, SMEM_TOTAL>>>(eidx, out);
}

// round 12
// speedup vs baseline: 1.0020x; 1.0020x over previous
#include <cuda_runtime.h>
#include <cuda_fp16.h>
#include <math.h>
#include <stdint.h>

#define MR 2
#define NE 8
#define CD 1024
#define DD 256
#define BB 32
#define SS 512
// stage (16KB): A 8K ([128 m][32 k], row-swizzled) | B 8K ([32 k][128 n], chunk-swizzled)
#define STAGE_BYTES 16384
#define OFF_B  8192
#define SMEM_TOTAL (4 * STAGE_BYTES)   // 65536; 2 CTAs/SM

typedef __half fp16;

// ---------------- static device scratch (no allocs) ----------------
__device__ fp16 g_x[(size_t)BB * SS * CD];         // x fp16 (C contiguous)
__device__ fp16 g_z[(size_t)MR * BB * SS * DD];    // z fp16 (D contiguous)
__device__ fp16 g_dw16[(size_t)MR * NE * CD * DD]; // dw fp16, NATIVE [C][D]
__device__ fp16 g_uw16[(size_t)MR * NE * DD * CD]; // uw fp16, NATIVE [D][C]

// ---------------- ptx helpers ----------------
__device__ __forceinline__ uint32_t smem_u32(const void* p) {
    uint32_t a;
    asm("{ .reg .u64 t; cvta.to.shared.u64 t, %1; cvt.u32.u64 %0, t; }" : "=r"(a) : "l"(p));
    return a;
}
#define CP16(dst, src) \
    asm volatile("cp.async.cg.shared.global [%0], [%1], 16;" :: "r"(dst), "l"(src))
#define CP_COMMIT() asm volatile("cp.async.commit_group;")
#define CP_WAIT1()  asm volatile("cp.async.wait_group 1;")
#define CP_WAIT0()  asm volatile("cp.async.wait_group 0;")

#define LDSM4(r, a) \
    asm volatile("ldmatrix.sync.aligned.m8n8.x4.shared.b16 {%0,%1,%2,%3}, [%4];" \
        : "=r"((r)[0]), "=r"((r)[1]), "=r"((r)[2]), "=r"((r)[3]) : "r"(a))
#define LDSM4T(r, a) \
    asm volatile("ldmatrix.sync.aligned.m8n8.x4.trans.shared.b16 {%0,%1,%2,%3}, [%4];" \
        : "=r"((r)[0]), "=r"((r)[1]), "=r"((r)[2]), "=r"((r)[3]) : "r"(a))

#define MMA(d, a, b0, b1) \
    asm volatile("mma.sync.aligned.m16n8k16.row.col.f32.f16.f16.f32 " \
        "{%0,%1,%2,%3},{%4,%5,%6,%7},{%8,%9},{%0,%1,%2,%3};" \
        : "+f"((d)[0]), "+f"((d)[1]), "+f"((d)[2]), "+f"((d)[3]) \
        : "r"((a)[0]), "r"((a)[1]), "r"((a)[2]), "r"((a)[3]), "r"(b0), "r"(b1))

// A-side swizzle: 64B rows (4 x 16B chunks)
__device__ __forceinline__ uint32_t swz(uint32_t row, uint32_t chunk) {
    return row * 64u + ((chunk ^ ((row >> 1) & 3u)) << 4);
}
// B-side (K-major) swizzle: 256B rows (16 x 16B chunks), chunk ^= row&7
__device__ __forceinline__ uint32_t bswz(uint32_t row, uint32_t chunk) {
    return row * 256u + ((chunk ^ (row & 7u)) << 4);
}

// ---------------- stage loader: 4x cp.async(16B) per thread ----------------
__device__ __forceinline__ void stage_load(uint32_t sbase,
                                           const fp16* __restrict__ A1, int lda,
                                           const fp16* __restrict__ Bg, int ldb,
                                           int ncol0, int kc, int tid) {
    #pragma unroll
    for (int i = 0; i < 2; i++) {
        int q = tid + (i << 8);
        {   // A chunk: 512 = 128 rows x 4 chunks
            int r = q >> 2, c = q & 3;
            CP16(sbase + swz(r, c), A1 + (size_t)r * lda + kc + c * 8);
        }
        {   // B chunk: 512 = 32 rows x 16 chunks
            int r = q >> 4, c = q & 15;
            CP16(sbase + OFF_B + bswz(r, c),
                 Bg + (size_t)(kc + r) * ldb + ncol0 + c * 8);
        }
    }
}

// frag loads for one half-step (6 LDSM) into buffer slot
#define LOAD_FRAGS(abuf, bbuf, abase, bbase) do { \
    LDSM4T((bbuf)[0], (bbase) + b0); \
    LDSM4T((bbuf)[1], (bbase) + b1); \
    LDSM4((abuf)[0], (abase)); \
    LDSM4((abuf)[1], (abase) + 1024); \
    LDSM4((abuf)[2], (abase) + 2048); \
    LDSM4((abuf)[3], (abase) + 3072); \
} while (0)

#define MMA_BURST(abuf, bbuf) do { \
    _Pragma("unroll") \
    for (int mt = 0; mt < 4; mt++) \
        _Pragma("unroll") \
        for (int nt = 0; nt < 4; nt++) \
            MMA(acc[mt][nt], (abuf)[mt], \
                (bbuf)[nt >> 1][2 * (nt & 1)], (bbuf)[nt >> 1][2 * (nt & 1) + 1]); \
} while (0)

// ---------------- GEMM mainloop: warp 64x32, double-buffered fragments --------
template <int NK>
__device__ __forceinline__ void gemm_main(uint32_t smem_b,
                                          const fp16* __restrict__ A1, int lda,
                                          const fp16* __restrict__ Bg, int ldb,
                                          int ncol0, float acc[4][4][4], int tid) {
    const int lane = tid & 31, warp = tid >> 5;
    const int wm = (warp & 1) * 64, wn = (warp >> 1) * 32;
    const int r15 = lane & 15, chi = lane >> 4;

    const uint32_t a0 = swz((uint32_t)(wm + r15), (uint32_t)chi);
    const uint32_t b0 = OFF_B + bswz((uint32_t)r15, (uint32_t)((wn >> 3) + chi));
    const uint32_t b1 = OFF_B + bswz((uint32_t)r15, (uint32_t)((wn >> 3) + 2 + chi));

    stage_load(smem_b,                   A1, lda, Bg, ldb, ncol0, 0,  tid);  CP_COMMIT();
    stage_load(smem_b + STAGE_BYTES,     A1, lda, Bg, ldb, ncol0, 32, tid);  CP_COMMIT();
    stage_load(smem_b + 2 * STAGE_BYTES, A1, lda, Bg, ldb, ncol0, 64, tid);  CP_COMMIT();
    CP_WAIT1();        // stages 0 and 1 complete
    __syncthreads();   // visible to all threads

    uint32_t ah[2][4][4], bb[2][2][4];   // ping-pong fragment buffers
    LOAD_FRAGS(ah[0], bb[0], smem_b + a0, smem_b);   // stage 0, ks0

    for (int k = 0; k < NK; k++) {
        if (k > 0) {
            if (k + 3 <= NK) { CP_WAIT1(); } else { CP_WAIT0(); }
            __syncthreads();   // stages k, k+1 visible; frees slot (k+3)&3
        }
        if (k + 3 < NK) {
            stage_load(smem_b + (((k + 3) & 3) << 14), A1, lda, Bg, ldb, ncol0,
                       (k + 3) * 32, tid);
            CP_COMMIT();
        }
        const uint32_t stg = smem_b + ((k & 3) << 14);
        // hs0: prefetch ks1 (same stage) into buf1, run MMAs on buf0
        LOAD_FRAGS(ah[1], bb[1], stg + (a0 ^ 32u) /*A ks1*/, stg + 4096u /*B ks1*/);
        MMA_BURST(ah[0], bb[0]);
        // hs1: prefetch next-iter ks0 (stage k+1) into buf0, run MMAs on buf1
        const uint32_t sn = (k + 1 < NK) ? smem_b + (((k + 1) & 3) << 14) : stg;
        LOAD_FRAGS(ah[0], bb[0], sn + a0, sn);
        MMA_BURST(ah[1], bb[1]);
    }
}

// ---------------- down: z = silu(x @ dw + db), fp16 z -------------------------
__global__ void __launch_bounds__(256, 2)
down_mma(const int* __restrict__ eidx, const float* __restrict__ db) {
    extern __shared__ char smem[];
    uint32_t smem_b = smem_u32(smem);
    const int tid = threadIdx.x, lane = tid & 31, warp = tid >> 5;
    const int wm = (warp & 1) * 64, wn = (warp >> 1) * 32;
    const int stile = blockIdx.x >> 1, ntile = blockIdx.x & 1;
    const int b = blockIdx.y, m = blockIdx.z;
    const int e = eidx[m * BB + b];

    const fp16* A1 = g_x    + ((size_t)b * SS + stile * 128) * CD;
    const fp16* Bg = g_dw16 + (size_t)(m * NE + e) * CD * DD;   // [C][D] K-major

    float acc[4][4][4];
    #pragma unroll
    for (int i = 0; i < 4; i++)
        #pragma unroll
        for (int j = 0; j < 4; j++)
            #pragma unroll
            for (int q = 0; q < 4; q++) acc[i][j][q] = 0.f;

    gemm_main<CD / 32>(smem_b, A1, CD, Bg, DD, ntile * 128, acc, tid);

    const float* bias = db + (size_t)(m * NE + e) * DD;
    const size_t zrow0 = ((size_t)(m * BB + b) * SS + stile * 128);
    const int r0 = lane >> 2, cp = 2 * (lane & 3);

    #pragma unroll
    for (int mt = 0; mt < 4; mt++) {
        #pragma unroll
        for (int nt = 0; nt < 4; nt++) {
            const int col = ntile * 128 + wn + nt * 8 + cp;
            const float2 bv = *reinterpret_cast<const float2*>(bias + col);
            #pragma unroll
            for (int h = 0; h < 2; h++) {
                float v0 = acc[mt][nt][2 * h + 0] + bv.x;
                float v1 = acc[mt][nt][2 * h + 1] + bv.y;
                v0 = v0 / (1.f + __expf(-v0));
                v1 = v1 / (1.f + __expf(-v1));
                __half2 hp; hp.x = __float2half(v0); hp.y = __float2half(v1);
                *reinterpret_cast<__half2*>(
                    g_z + (zrow0 + wm + mt * 16 + r0 + h * 8) * DD + col) = hp;
            }
        }
    }
}

// ---------------- up: out = z @ uw (fp32 out) --------------------------------
__global__ void __launch_bounds__(256, 2)
up_mma(const int* __restrict__ eidx, float* __restrict__ out) {
    extern __shared__ char smem[];
    uint32_t smem_b = smem_u32(smem);
    const int tid = threadIdx.x, lane = tid & 31, warp = tid >> 5;
    const int wm = (warp & 1) * 64, wn = (warp >> 1) * 32;
    const int stile = blockIdx.x & 3, ctile = blockIdx.x >> 2;
    const int b = blockIdx.y, m = blockIdx.z;
    const int e = eidx[m * BB + b];

    const fp16* A1 = g_z    + ((size_t)(m * BB + b) * SS + stile * 128) * DD;
    const fp16* Bg = g_uw16 + (size_t)(m * NE + e) * DD * CD;   // [D][C] K-major

    float acc[4][4][4];
    #pragma unroll
    for (int i = 0; i < 4; i++)
        #pragma unroll
        for (int j = 0; j < 4; j++)
            #pragma unroll
            for (int q = 0; q < 4; q++) acc[i][j][q] = 0.f;

    gemm_main<DD / 32>(smem_b, A1, DD, Bg, CD, ctile * 128, acc, tid);

    const size_t orow0 = ((size_t)(m * BB + b) * SS + stile * 128);
    const int r0 = lane >> 2, cp = 2 * (lane & 3);

    #pragma unroll
    for (int mt = 0; mt < 4; mt++) {
        #pragma unroll
        for (int nt = 0; nt < 4; nt++) {
            const int col = ctile * 128 + wn + nt * 8 + cp;
            #pragma unroll
            for (int h = 0; h < 2; h++) {
                const size_t off = (orow0 + wm + mt * 16 + r0 + h * 8) * CD + col;
                *reinterpret_cast<float2*>(out + off) =
                    make_float2(acc[mt][nt][2 * h + 0], acc[mt][nt][2 * h + 1]);
            }
        }
    }
}

// ---------------- prep: fused fp32 -> fp16 conversion of x, dw, uw ------------
#define NX4 ((size_t)BB * SS * CD / 4)
#define NW4 ((size_t)MR * NE * CD * DD / 4)
__global__ void __launch_bounds__(256)
cvt_all(const float* __restrict__ x, const float* __restrict__ dw,
        const float* __restrict__ uw) {
    size_t g = (size_t)blockIdx.x * 256 + threadIdx.x;
    const float* src; fp16* dst; size_t i;
    if (g < NX4)            { src = x;  dst = g_x;    i = g; }
    else if (g < NX4 + NW4) { src = dw; dst = g_dw16; i = g - NX4; }
    else                    { src = uw; dst = g_uw16; i = g - NX4 - NW4; }
    float4 v = *reinterpret_cast<const float4*>(src + i * 4);
    __half2 p0, p1;
    p0.x = __float2half(v.x); p0.y = __float2half(v.y);
    p1.x = __float2half(v.z); p1.y = __float2half(v.w);
    *reinterpret_cast<uint2*>(dst + i * 4) =
        make_uint2(*reinterpret_cast<uint32_t*>(&p0), *reinterpret_cast<uint32_t*>(&p1));
}

// ---------------- launch ------------------------------------------------------
extern "C" void kernel_launch(void* const* d_in, const int* in_sizes, int n_in,
                              void* d_out, int out_size) {
    const float* x    = (const float*)d_in[0];   // [B,S,C]
    const int*   eidx = (const int*)d_in[1];     // [M,B]
    const float* dw   = (const float*)d_in[2];   // [M,N,C,D]
    const float* db   = (const float*)d_in[3];   // [M,N,D]
    const float* uw   = (const float*)d_in[4];   // [M,N,D,C]
    float*       out  = (float*)d_out;           // [M,B,S,C]

    cudaFuncSetAttribute(down_mma, cudaFuncAttributeMaxDynamicSharedMemorySize, SMEM_TOTAL);
    cudaFuncSetAttribute(up_mma,   cudaFuncAttributeMaxDynamicSharedMemorySize, SMEM_TOTAL);

    cvt_all<<<(unsigned)((NX4 + 2 * NW4) / 256), 256>>>(x, dw, uw);

    down_mma<<<dim3(8, BB, MR), 256, SMEM_TOTAL>>>(eidx, db);
    up_mma<<<dim3(32, BB, MR), 256, SMEM_TOTAL>>>(eidx, out);
}

// round 13
// speedup vs baseline: 1.0336x; 1.0315x over previous
#include <cuda_runtime.h>
#include <cuda_fp16.h>
#include <math.h>
#include <stdint.h>

#define MR 2
#define NE 8
#define CD 1024
#define DD 256
#define BB 32
#define SS 512
#define STAGES 6
// stage (16KB): A 8K ([128 m][32 k], row-swizzled) | B 8K ([32 k][128 n], chunk-swizzled)
#define STAGE_BYTES 16384
#define OFF_B  8192
#define RING_BYTES (STAGES * STAGE_BYTES)   // 98304; 2 CTAs/SM = 192KB

typedef __half fp16;

// ---------------- static device scratch (no allocs) ----------------
__device__ fp16 g_x[(size_t)BB * SS * CD];         // x fp16 (C contiguous)
__device__ fp16 g_z[(size_t)MR * BB * SS * DD];    // z fp16 (D contiguous)
__device__ fp16 g_dw16[(size_t)MR * NE * CD * DD]; // dw fp16, NATIVE [C][D]
__device__ fp16 g_uw16[(size_t)MR * NE * DD * CD]; // uw fp16, NATIVE [D][C]

// ---------------- ptx helpers ----------------
__device__ __forceinline__ uint32_t smem_u32(const void* p) {
    uint32_t a;
    asm("{ .reg .u64 t; cvta.to.shared.u64 t, %1; cvt.u32.u64 %0, t; }" : "=r"(a) : "l"(p));
    return a;
}
#define CP16(dst, src) \
    asm volatile("cp.async.cg.shared.global [%0], [%1], 16;" :: "r"(dst), "l"(src))
#define CP_COMMIT() asm volatile("cp.async.commit_group;")
#define CP_WAIT4()  asm volatile("cp.async.wait_group 4;")
#define CP_WAIT3()  asm volatile("cp.async.wait_group 3;")
#define CP_WAIT2()  asm volatile("cp.async.wait_group 2;")
#define CP_WAIT1()  asm volatile("cp.async.wait_group 1;")
#define CP_WAIT0()  asm volatile("cp.async.wait_group 0;")

#define LDSM4(r, a) \
    asm volatile("ldmatrix.sync.aligned.m8n8.x4.shared.b16 {%0,%1,%2,%3}, [%4];" \
        : "=r"((r)[0]), "=r"((r)[1]), "=r"((r)[2]), "=r"((r)[3]) : "r"(a))
#define LDSM4T(r, a) \
    asm volatile("ldmatrix.sync.aligned.m8n8.x4.trans.shared.b16 {%0,%1,%2,%3}, [%4];" \
        : "=r"((r)[0]), "=r"((r)[1]), "=r"((r)[2]), "=r"((r)[3]) : "r"(a))

#define MMA(d, a, b0, b1) \
    asm volatile("mma.sync.aligned.m16n8k16.row.col.f32.f16.f16.f32 " \
        "{%0,%1,%2,%3},{%4,%5,%6,%7},{%8,%9},{%0,%1,%2,%3};" \
        : "+f"((d)[0]), "+f"((d)[1]), "+f"((d)[2]), "+f"((d)[3]) \
        : "r"((a)[0]), "r"((a)[1]), "r"((a)[2]), "r"((a)[3]), "r"(b0), "r"(b1))

// A-side swizzle: 64B rows (4 x 16B chunks)
__device__ __forceinline__ uint32_t swz(uint32_t row, uint32_t chunk) {
    return row * 64u + ((chunk ^ ((row >> 1) & 3u)) << 4);
}
// B-side (K-major) swizzle: 256B rows (16 x 16B chunks), chunk ^= row&7
__device__ __forceinline__ uint32_t bswz(uint32_t row, uint32_t chunk) {
    return row * 256u + ((chunk ^ (row & 7u)) << 4);
}

// ---------------- stage loader: 4x cp.async(16B) per thread ----------------
__device__ __forceinline__ void stage_load(uint32_t sbase,
                                           const fp16* __restrict__ A1, int lda,
                                           const fp16* __restrict__ Bg, int ldb,
                                           int ncol0, int kc, int tid) {
    #pragma unroll
    for (int i = 0; i < 2; i++) {
        int q = tid + (i << 8);
        {   // A chunk: 512 = 128 rows x 4 chunks
            int r = q >> 2, c = q & 3;
            CP16(sbase + swz(r, c), A1 + (size_t)r * lda + kc + c * 8);
        }
        {   // B chunk: 512 = 32 rows x 16 chunks
            int r = q >> 4, c = q & 15;
            CP16(sbase + OFF_B + bswz(r, c),
                 Bg + (size_t)(kc + r) * ldb + ncol0 + c * 8);
        }
    }
}

// ---------------- GEMM mainloop: warp 64x32; ring=6, lookahead=4 --------------
// Loads for stage k+4 issue at the TOP of iter k, BEFORE the barrier: with a
// 6-slot ring that slot was last read at iter k-2, which every warp finished
// before barrier(k-1) -- write-before-this-barrier is race-free.
template <int NK>
__device__ __forceinline__ void gemm_main(uint32_t smem_b,
                                          const fp16* __restrict__ A1, int lda,
                                          const fp16* __restrict__ Bg, int ldb,
                                          int ncol0, float acc[4][4][4], int tid) {
    const int lane = tid & 31, warp = tid >> 5;
    const int wm = (warp & 1) * 64, wn = (warp >> 1) * 32;
    const int r15 = lane & 15, chi = lane >> 4;

    const uint32_t a0 = swz((uint32_t)(wm + r15), (uint32_t)chi);
    const uint32_t b0 = OFF_B + bswz((uint32_t)r15, (uint32_t)((wn >> 3) + chi));
    const uint32_t b1 = OFF_B + bswz((uint32_t)r15, (uint32_t)((wn >> 3) + 2 + chi));

    // prologue: 4 stages in flight
    #pragma unroll
    for (int s = 0; s < 4; s++) {
        stage_load(smem_b + s * STAGE_BYTES, A1, lda, Bg, ldb, ncol0, s * 32, tid);
        CP_COMMIT();
    }

    uint32_t ah[4][4], bb[2][4];
    uint32_t cur = 0, pre = 4 * STAGE_BYTES;   // ring byte-offsets

    for (int k = 0; k < NK; k++) {
        // issue stage k+4 first (slot `pre` is free; see invariant above)
        if (k + 4 < NK) {
            stage_load(smem_b + pre, A1, lda, Bg, ldb, ncol0, (k + 4) * 32, tid);
            CP_COMMIT();
            pre += STAGE_BYTES; if (pre == RING_BYTES) pre = 0;
        }
        // wait until group k complete (pending = groups committed beyond k)
        if      (k + 5 <= NK) { CP_WAIT4(); }
        else if (k + 4 <= NK) { CP_WAIT3(); }
        else if (k + 3 <= NK) { CP_WAIT2(); }
        else if (k + 2 <= NK) { CP_WAIT1(); }
        else                  { CP_WAIT0(); }
        __syncthreads();   // stage k visible to all threads

        const uint32_t stg = smem_b + cur;
        cur += STAGE_BYTES; if (cur == RING_BYTES) cur = 0;

        #pragma unroll
        for (int ks = 0; ks < 2; ks++) {
            const uint32_t ax = stg + (ks ? (a0 ^ 32u) : a0);
            const uint32_t bof = stg + (ks ? 4096u : 0u);
            LDSM4T(bb[0], bof + b0);
            LDSM4T(bb[1], bof + b1);
            LDSM4(ah[0], ax);
            LDSM4(ah[1], ax + 1024);
            LDSM4(ah[2], ax + 2048);
            LDSM4(ah[3], ax + 3072);
            #pragma unroll
            for (int mt = 0; mt < 4; mt++)
                #pragma unroll
                for (int nt = 0; nt < 4; nt++)
                    MMA(acc[mt][nt], ah[mt],
                        bb[nt >> 1][2 * (nt & 1)], bb[nt >> 1][2 * (nt & 1) + 1]);
        }
    }
}

// ---------------- down: z = silu(x @ dw + db), fp16 z -------------------------
__global__ void __launch_bounds__(256, 2)
down_mma(const int* __restrict__ eidx, const float* __restrict__ db) {
    extern __shared__ char smem[];
    uint32_t smem_b = smem_u32(smem);
    const int tid = threadIdx.x, lane = tid & 31, warp = tid >> 5;
    const int wm = (warp & 1) * 64, wn = (warp >> 1) * 32;
    const int stile = blockIdx.x >> 1, ntile = blockIdx.x & 1;
    const int b = blockIdx.y, m = blockIdx.z;
    const int e = eidx[m * BB + b];

    const fp16* A1 = g_x    + ((size_t)b * SS + stile * 128) * CD;
    const fp16* Bg = g_dw16 + (size_t)(m * NE + e) * CD * DD;   // [C][D] K-major

    float acc[4][4][4];
    #pragma unroll
    for (int i = 0; i < 4; i++)
        #pragma unroll
        for (int j = 0; j < 4; j++)
            #pragma unroll
            for (int q = 0; q < 4; q++) acc[i][j][q] = 0.f;

    gemm_main<CD / 32>(smem_b, A1, CD, Bg, DD, ntile * 128, acc, tid);

    const float* bias = db + (size_t)(m * NE + e) * DD;
    const size_t zrow0 = ((size_t)(m * BB + b) * SS + stile * 128);
    const int r0 = lane >> 2, cp = 2 * (lane & 3);

    #pragma unroll
    for (int mt = 0; mt < 4; mt++) {
        #pragma unroll
        for (int nt = 0; nt < 4; nt++) {
            const int col = ntile * 128 + wn + nt * 8 + cp;
            const float2 bv = *reinterpret_cast<const float2*>(bias + col);
            #pragma unroll
            for (int h = 0; h < 2; h++) {
                float v0 = acc[mt][nt][2 * h + 0] + bv.x;
                float v1 = acc[mt][nt][2 * h + 1] + bv.y;
                v0 = v0 / (1.f + __expf(-v0));
                v1 = v1 / (1.f + __expf(-v1));
                __half2 hp; hp.x = __float2half(v0); hp.y = __float2half(v1);
                *reinterpret_cast<__half2*>(
                    g_z + (zrow0 + wm + mt * 16 + r0 + h * 8) * DD + col) = hp;
            }
        }
    }
}

// ---------------- up: out = z @ uw (fp32 out) --------------------------------
__global__ void __launch_bounds__(256, 2)
up_mma(const int* __restrict__ eidx, float* __restrict__ out) {
    extern __shared__ char smem[];
    uint32_t smem_b = smem_u32(smem);
    const int tid = threadIdx.x, lane = tid & 31, warp = tid >> 5;
    const int wm = (warp & 1) * 64, wn = (warp >> 1) * 32;
    const int stile = blockIdx.x & 3, ctile = blockIdx.x >> 2;
    const int b = blockIdx.y, m = blockIdx.z;
    const int e = eidx[m * BB + b];

    const fp16* A1 = g_z    + ((size_t)(m * BB + b) * SS + stile * 128) * DD;
    const fp16* Bg = g_uw16 + (size_t)(m * NE + e) * DD * CD;   // [D][C] K-major

    float acc[4][4][4];
    #pragma unroll
    for (int i = 0; i < 4; i++)
        #pragma unroll
        for (int j = 0; j < 4; j++)
            #pragma unroll
            for (int q = 0; q < 4; q++) acc[i][j][q] = 0.f;

    gemm_main<DD / 32>(smem_b, A1, DD, Bg, CD, ctile * 128, acc, tid);

    const size_t orow0 = ((size_t)(m * BB + b) * SS + stile * 128);
    const int r0 = lane >> 2, cp = 2 * (lane & 3);

    #pragma unroll
    for (int mt = 0; mt < 4; mt++) {
        #pragma unroll
        for (int nt = 0; nt < 4; nt++) {
            const int col = ctile * 128 + wn + nt * 8 + cp;
            #pragma unroll
            for (int h = 0; h < 2; h++) {
                const size_t off = (orow0 + wm + mt * 16 + r0 + h * 8) * CD + col;
                *reinterpret_cast<float2*>(out + off) =
                    make_float2(acc[mt][nt][2 * h + 0], acc[mt][nt][2 * h + 1]);
            }
        }
    }
}

// ---------------- prep: fused fp32 -> fp16 conversion of x, dw, uw ------------
#define NX4 ((size_t)BB * SS * CD / 4)
#define NW4 ((size_t)MR * NE * CD * DD / 4)
__global__ void __launch_bounds__(256)
cvt_all(const float* __restrict__ x, const float* __restrict__ dw,
        const float* __restrict__ uw) {
    size_t g = (size_t)blockIdx.x * 256 + threadIdx.x;
    const float* src; fp16* dst; size_t i;
    if (g < NX4)            { src = x;  dst = g_x;    i = g; }
    else if (g < NX4 + NW4) { src = dw; dst = g_dw16; i = g - NX4; }
    else                    { src = uw; dst = g_uw16; i = g - NX4 - NW4; }
    float4 v = *reinterpret_cast<const float4*>(src + i * 4);
    __half2 p0, p1;
    p0.x = __float2half(v.x); p0.y = __float2half(v.y);
    p1.x = __float2half(v.z); p1.y = __float2half(v.w);
    *reinterpret_cast<uint2*>(dst + i * 4) =
        make_uint2(*reinterpret_cast<uint32_t*>(&p0), *reinterpret_cast<uint32_t*>(&p1));
}

// ---------------- launch ------------------------------------------------------
extern "C" void kernel_launch(void* const* d_in, const int* in_sizes, int n_in,
                              void* d_out, int out_size) {
    const float* x    = (const float*)d_in[0];   // [B,S,C]
    const int*   eidx = (const int*)d_in[1];     // [M,B]
    const float* dw   = (const float*)d_in[2];   // [M,N,C,D]
    const float* db   = (const float*)d_in[3];   // [M,N,D]
    const float* uw   = (const float*)d_in[4];   // [M,N,D,C]
    float*       out  = (float*)d_out;           // [M,B,S,C]

    cudaFuncSetAttribute(down_mma, cudaFuncAttributeMaxDynamicSharedMemorySize, RING_BYTES);
    cudaFuncSetAttribute(up_mma,   cudaFuncAttributeMaxDynamicSharedMemorySize, RING_BYTES);

    cvt_all<<<(unsigned)((NX4 + 2 * NW4) / 256), 256>>>(x, dw, uw);

    down_mma<<<dim3(8, BB, MR), 256, RING_BYTES>>>(eidx, db);
    up_mma<<<dim3(32, BB, MR), 256, RING_BYTES>>>(eidx, out);
}

// round 14
// speedup vs baseline: 1.1046x; 1.0686x over previous
#include <cuda_runtime.h>
#include <cuda_fp16.h>
#include <math.h>
#include <stdint.h>

#define MR 2
#define NE 8
#define CD 1024
#define DD 256
#define BB 32
#define SS 512
#define STAGES 6
// stage (16KB): A 8K ([128 m][32 k], row-swizzled) | B 8K ([32 k][128 n], chunk-swizzled)
#define STAGE_BYTES 16384
#define OFF_B  8192
#define RING_BYTES (STAGES * STAGE_BYTES)   // 98304; 2 CTAs/SM = 192KB

typedef __half fp16;

// ---------------- static device scratch (no allocs) ----------------
__device__ fp16 g_x[(size_t)BB * SS * CD];         // x fp16 (C contiguous)
__device__ fp16 g_z[(size_t)MR * BB * SS * DD];    // z fp16 (D contiguous)
__device__ fp16 g_dw16[(size_t)MR * NE * CD * DD]; // dw fp16, NATIVE [C][D]
__device__ fp16 g_uw16[(size_t)MR * NE * DD * CD]; // uw fp16, NATIVE [D][C]
// per-z-tile readiness flags (zero-init; self-resetting across graph replays)
__device__ int g_ready[MR * BB * (SS / 128)];
__device__ int g_done [MR * BB * (SS / 128)];

// ---------------- ptx helpers ----------------
__device__ __forceinline__ uint32_t smem_u32(const void* p) {
    uint32_t a;
    asm("{ .reg .u64 t; cvta.to.shared.u64 t, %1; cvt.u32.u64 %0, t; }" : "=r"(a) : "l"(p));
    return a;
}
#define CP16(dst, src) \
    asm volatile("cp.async.cg.shared.global [%0], [%1], 16;" :: "r"(dst), "l"(src))
#define CP_COMMIT() asm volatile("cp.async.commit_group;")
#define CP_WAIT4()  asm volatile("cp.async.wait_group 4;")
#define CP_WAIT3()  asm volatile("cp.async.wait_group 3;")
#define CP_WAIT2()  asm volatile("cp.async.wait_group 2;")
#define CP_WAIT1()  asm volatile("cp.async.wait_group 1;")
#define CP_WAIT0()  asm volatile("cp.async.wait_group 0;")

#define LDSM4(r, a) \
    asm volatile("ldmatrix.sync.aligned.m8n8.x4.shared.b16 {%0,%1,%2,%3}, [%4];" \
        : "=r"((r)[0]), "=r"((r)[1]), "=r"((r)[2]), "=r"((r)[3]) : "r"(a))
#define LDSM4T(r, a) \
    asm volatile("ldmatrix.sync.aligned.m8n8.x4.trans.shared.b16 {%0,%1,%2,%3}, [%4];" \
        : "=r"((r)[0]), "=r"((r)[1]), "=r"((r)[2]), "=r"((r)[3]) : "r"(a))

#define MMA(d, a, b0, b1) \
    asm volatile("mma.sync.aligned.m16n8k16.row.col.f32.f16.f16.f32 " \
        "{%0,%1,%2,%3},{%4,%5,%6,%7},{%8,%9},{%0,%1,%2,%3};" \
        : "+f"((d)[0]), "+f"((d)[1]), "+f"((d)[2]), "+f"((d)[3]) \
        : "r"((a)[0]), "r"((a)[1]), "r"((a)[2]), "r"((a)[3]), "r"(b0), "r"(b1))

// A-side swizzle: 64B rows (4 x 16B chunks)
__device__ __forceinline__ uint32_t swz(uint32_t row, uint32_t chunk) {
    return row * 64u + ((chunk ^ ((row >> 1) & 3u)) << 4);
}
// B-side (K-major) swizzle: 256B rows (16 x 16B chunks), chunk ^= row&7
__device__ __forceinline__ uint32_t bswz(uint32_t row, uint32_t chunk) {
    return row * 256u + ((chunk ^ (row & 7u)) << 4);
}

// ---------------- stage loader: 4x cp.async(16B) per thread ----------------
__device__ __forceinline__ void stage_load(uint32_t sbase,
                                           const fp16* __restrict__ A1, int lda,
                                           const fp16* __restrict__ Bg, int ldb,
                                           int ncol0, int kc, int tid) {
    #pragma unroll
    for (int i = 0; i < 2; i++) {
        int q = tid + (i << 8);
        {   // A chunk: 512 = 128 rows x 4 chunks
            int r = q >> 2, c = q & 3;
            CP16(sbase + swz(r, c), A1 + (size_t)r * lda + kc + c * 8);
        }
        {   // B chunk: 512 = 32 rows x 16 chunks
            int r = q >> 4, c = q & 15;
            CP16(sbase + OFF_B + bswz(r, c),
                 Bg + (size_t)(kc + r) * ldb + ncol0 + c * 8);
        }
    }
}

// ---------------- GEMM mainloop: warp 64x32; ring=6, lookahead=4 --------------
template <int NK>
__device__ __forceinline__ void gemm_main(uint32_t smem_b,
                                          const fp16* __restrict__ A1, int lda,
                                          const fp16* __restrict__ Bg, int ldb,
                                          int ncol0, float acc[4][4][4], int tid) {
    const int lane = tid & 31, warp = tid >> 5;
    const int wm = (warp & 1) * 64, wn = (warp >> 1) * 32;
    const int r15 = lane & 15, chi = lane >> 4;

    const uint32_t a0 = swz((uint32_t)(wm + r15), (uint32_t)chi);
    const uint32_t b0 = OFF_B + bswz((uint32_t)r15, (uint32_t)((wn >> 3) + chi));
    const uint32_t b1 = OFF_B + bswz((uint32_t)r15, (uint32_t)((wn >> 3) + 2 + chi));

    #pragma unroll
    for (int s = 0; s < 4; s++) {
        stage_load(smem_b + s * STAGE_BYTES, A1, lda, Bg, ldb, ncol0, s * 32, tid);
        CP_COMMIT();
    }

    uint32_t ah[4][4], bb[2][4];
    uint32_t cur = 0, pre = 4 * STAGE_BYTES;

    for (int k = 0; k < NK; k++) {
        if (k + 4 < NK) {
            stage_load(smem_b + pre, A1, lda, Bg, ldb, ncol0, (k + 4) * 32, tid);
            CP_COMMIT();
            pre += STAGE_BYTES; if (pre == RING_BYTES) pre = 0;
        }
        if      (k + 5 <= NK) { CP_WAIT4(); }
        else if (k + 4 <= NK) { CP_WAIT3(); }
        else if (k + 3 <= NK) { CP_WAIT2(); }
        else if (k + 2 <= NK) { CP_WAIT1(); }
        else                  { CP_WAIT0(); }
        __syncthreads();

        const uint32_t stg = smem_b + cur;
        cur += STAGE_BYTES; if (cur == RING_BYTES) cur = 0;

        #pragma unroll
        for (int ks = 0; ks < 2; ks++) {
            const uint32_t ax = stg + (ks ? (a0 ^ 32u) : a0);
            const uint32_t bof = stg + (ks ? 4096u : 0u);
            LDSM4T(bb[0], bof + b0);
            LDSM4T(bb[1], bof + b1);
            LDSM4(ah[0], ax);
            LDSM4(ah[1], ax + 1024);
            LDSM4(ah[2], ax + 2048);
            LDSM4(ah[3], ax + 3072);
            #pragma unroll
            for (int mt = 0; mt < 4; mt++)
                #pragma unroll
                for (int nt = 0; nt < 4; nt++)
                    MMA(acc[mt][nt], ah[mt],
                        bb[nt >> 1][2 * (nt & 1)], bb[nt >> 1][2 * (nt & 1) + 1]);
        }
    }
}

// ---------------- down: z = silu(x @ dw + db), fp16 z; sets ready flag --------
__global__ void __launch_bounds__(256, 2)
down_mma(const int* __restrict__ eidx, const float* __restrict__ db) {
    extern __shared__ char smem[];
    uint32_t smem_b = smem_u32(smem);
    const int tid = threadIdx.x, lane = tid & 31, warp = tid >> 5;
    const int wm = (warp & 1) * 64, wn = (warp >> 1) * 32;
    const int stile = blockIdx.x >> 1, ntile = blockIdx.x & 1;
    const int b = blockIdx.y, m = blockIdx.z;
    const int e = eidx[m * BB + b];

#if __CUDA_ARCH__ >= 900
    // allow the PDL-attributed up kernel to become schedulable once every
    // down CTA is resident (deadlock-safe: down needs no further slots)
    if (tid == 0) cudaTriggerProgrammaticLaunchCompletion();
#endif

    const fp16* A1 = g_x    + ((size_t)b * SS + stile * 128) * CD;
    const fp16* Bg = g_dw16 + (size_t)(m * NE + e) * CD * DD;

    float acc[4][4][4];
    #pragma unroll
    for (int i = 0; i < 4; i++)
        #pragma unroll
        for (int j = 0; j < 4; j++)
            #pragma unroll
            for (int q = 0; q < 4; q++) acc[i][j][q] = 0.f;

    gemm_main<CD / 32>(smem_b, A1, CD, Bg, DD, ntile * 128, acc, tid);

    const float* bias = db + (size_t)(m * NE + e) * DD;
    const size_t zrow0 = ((size_t)(m * BB + b) * SS + stile * 128);
    const int r0 = lane >> 2, cp = 2 * (lane & 3);

    #pragma unroll
    for (int mt = 0; mt < 4; mt++) {
        #pragma unroll
        for (int nt = 0; nt < 4; nt++) {
            const int col = ntile * 128 + wn + nt * 8 + cp;
            const float2 bv = *reinterpret_cast<const float2*>(bias + col);
            #pragma unroll
            for (int h = 0; h < 2; h++) {
                float v0 = acc[mt][nt][2 * h + 0] + bv.x;
                float v1 = acc[mt][nt][2 * h + 1] + bv.y;
                v0 = v0 / (1.f + __expf(-v0));
                v1 = v1 / (1.f + __expf(-v1));
                __half2 hp; hp.x = __float2half(v0); hp.y = __float2half(v1);
                *reinterpret_cast<__half2*>(
                    g_z + (zrow0 + wm + mt * 16 + r0 + h * 8) * DD + col) = hp;
            }
        }
    }

    __syncthreads();   // all z stores of this CTA issued
    if (tid == 0) {
        __threadfence();   // publish z before the flag
        atomicAdd(&g_ready[(m * BB + b) * (SS / 128) + stile], 1);
    }
}

// ---------------- up: out = z @ uw (fp32 out); waits on ready flag ------------
__global__ void __launch_bounds__(256, 2)
up_mma(const int* __restrict__ eidx, float* __restrict__ out) {
    extern __shared__ char smem[];
    uint32_t smem_b = smem_u32(smem);
    const int tid = threadIdx.x, lane = tid & 31, warp = tid >> 5;
    const int wm = (warp & 1) * 64, wn = (warp >> 1) * 32;
    const int stile = blockIdx.x & 3, ctile = blockIdx.x >> 2;
    const int b = blockIdx.y, m = blockIdx.z;
    const int e = eidx[m * BB + b];
    const int fidx = (m * BB + b) * (SS / 128) + stile;

    // wait for both down ntiles of this z tile
    if (tid == 0) {
        while (atomicAdd(&g_ready[fidx], 0) < 2) __nanosleep(128);
    }
    __syncthreads();
    __threadfence();   // acquire side: order z reads after flag observation

    const fp16* A1 = g_z    + ((size_t)(m * BB + b) * SS + stile * 128) * DD;
    const fp16* Bg = g_uw16 + (size_t)(m * NE + e) * DD * CD;

    float acc[4][4][4];
    #pragma unroll
    for (int i = 0; i < 4; i++)
        #pragma unroll
        for (int j = 0; j < 4; j++)
            #pragma unroll
            for (int q = 0; q < 4; q++) acc[i][j][q] = 0.f;

    gemm_main<DD / 32>(smem_b, A1, DD, Bg, CD, ctile * 128, acc, tid);

    const size_t orow0 = ((size_t)(m * BB + b) * SS + stile * 128);
    const int r0 = lane >> 2, cp = 2 * (lane & 3);

    #pragma unroll
    for (int mt = 0; mt < 4; mt++) {
        #pragma unroll
        for (int nt = 0; nt < 4; nt++) {
            const int col = ctile * 128 + wn + nt * 8 + cp;
            #pragma unroll
            for (int h = 0; h < 2; h++) {
                const size_t off = (orow0 + wm + mt * 16 + r0 + h * 8) * CD + col;
                *reinterpret_cast<float2*>(out + off) =
                    make_float2(acc[mt][nt][2 * h + 0], acc[mt][nt][2 * h + 1]);
            }
        }
    }

    // self-reset flags so graph replays start from a clean state
    if (tid == 0) {
        int old = atomicAdd(&g_done[fidx], 1);
        if (old == (CD / 128) - 1) {        // 8th consumer of this z tile
            g_done[fidx] = 0;
            atomicExch(&g_ready[fidx], 0);
        }
    }
}

// ---------------- prep: fused fp32 -> fp16 conversion of x, dw, uw ------------
#define NX4 ((size_t)BB * SS * CD / 4)
#define NW4 ((size_t)MR * NE * CD * DD / 4)
__global__ void __launch_bounds__(256)
cvt_all(const float* __restrict__ x, const float* __restrict__ dw,
        const float* __restrict__ uw) {
    size_t g = (size_t)blockIdx.x * 256 + threadIdx.x;
    const float* src; fp16* dst; size_t i;
    if (g < NX4)            { src = x;  dst = g_x;    i = g; }
    else if (g < NX4 + NW4) { src = dw; dst = g_dw16; i = g - NX4; }
    else                    { src = uw; dst = g_uw16; i = g - NX4 - NW4; }
    float4 v = *reinterpret_cast<const float4*>(src + i * 4);
    __half2 p0, p1;
    p0.x = __float2half(v.x); p0.y = __float2half(v.y);
    p1.x = __float2half(v.z); p1.y = __float2half(v.w);
    *reinterpret_cast<uint2*>(dst + i * 4) =
        make_uint2(*reinterpret_cast<uint32_t*>(&p0), *reinterpret_cast<uint32_t*>(&p1));
}

// ---------------- launch ------------------------------------------------------
extern "C" void kernel_launch(void* const* d_in, const int* in_sizes, int n_in,
                              void* d_out, int out_size) {
    const float* x    = (const float*)d_in[0];   // [B,S,C]
    const int*   eidx = (const int*)d_in[1];     // [M,B]
    const float* db   = (const float*)d_in[3];   // [M,N,D]
    const float* dw   = (const float*)d_in[2];   // [M,N,C,D]
    const float* uw   = (const float*)d_in[4];   // [M,N,D,C]
    float*       out  = (float*)d_out;           // [M,B,S,C]

    cudaFuncSetAttribute(down_mma, cudaFuncAttributeMaxDynamicSharedMemorySize, RING_BYTES);
    cudaFuncSetAttribute(up_mma,   cudaFuncAttributeMaxDynamicSharedMemorySize, RING_BYTES);

    cvt_all<<<(unsigned)((NX4 + 2 * NW4) / 256), 256>>>(x, dw, uw);

    down_mma<<<dim3(8, BB, MR), 256, RING_BYTES>>>(eidx, db);

    // up: programmatic dependent launch -> CTAs fill SMs during down's tail,
    // per-tile flags enforce data readiness. Fallback: plain (serialized) launch.
    cudaLaunchConfig_t cfg = {};
    cfg.gridDim = dim3(32, BB, MR);
    cfg.blockDim = dim3(256, 1, 1);
    cfg.dynamicSmemBytes = RING_BYTES;
    cfg.stream = 0;
    cudaLaunchAttribute attrs[1];
    attrs[0].id = cudaLaunchAttributeProgrammaticStreamSerialization;
    attrs[0].val.programmaticStreamSerializationAllowed = 1;
    cfg.attrs = attrs;
    cfg.numAttrs = 1;
    cudaError_t err = cudaLaunchKernelEx(&cfg, up_mma, eidx, out);
    if (err != cudaSuccess) {
        up_mma<<<dim3(32, BB, MR), 256, RING_BYTES>>>(eidx, out);
    }
}